// round 1
// baseline (speedup 1.0000x reference)
#include <cuda_runtime.h>
#include <math.h>

#define N_NODES 50000
#define N_EDGES 800000

// ---------------- scratch (device globals; no dynamic allocation) -------------
__device__ float g_h[(size_t)N_NODES * 726];   // h buffer (layers 1,2 use 512 of 726 width)
__device__ float g_xa[(size_t)N_NODES * 512];  // res1 -> x2
__device__ float g_xb[(size_t)N_NODES * 512];  // x1 -> res3
__device__ float g_es[N_NODES * 6];
__device__ float g_ed[N_NODES * 6];
__device__ int   g_cnt[N_NODES + 1];
__device__ int   g_off[N_NODES + 1];
__device__ int   g_cur[N_NODES];
__device__ int   g_csr[N_EDGES];               // src node of each edge, grouped by dst

// ------------------------------- CSR build -----------------------------------
__global__ void k_zero_cnt() {
    int i = blockIdx.x * blockDim.x + threadIdx.x;
    if (i <= N_NODES) g_cnt[i] = 0;
}

__global__ void k_count(const int* __restrict__ edges) {
    int e = blockIdx.x * blockDim.x + threadIdx.x;
    if (e < N_EDGES) atomicAdd(&g_cnt[edges[2 * e + 1]], 1);
}

// single-block exclusive scan over 50001 entries
__global__ void k_scan() {
    __shared__ int sh[1024];
    __shared__ int carry_s;
    int tid = threadIdx.x;
    if (tid == 0) { carry_s = 0; g_off[0] = 0; }
    __syncthreads();
    for (int base = 0; base < N_NODES; base += 1024) {
        int i = base + tid;
        int v = (i < N_NODES) ? g_cnt[i] : 0;
        sh[tid] = v;
        __syncthreads();
        for (int d = 1; d < 1024; d <<= 1) {
            int t = (tid >= d) ? sh[tid - d] : 0;
            __syncthreads();
            sh[tid] += t;
            __syncthreads();
        }
        if (i < N_NODES) g_off[i + 1] = carry_s + sh[tid];
        __syncthreads();
        if (tid == 0) carry_s += sh[1023];
        __syncthreads();
    }
}

__global__ void k_initcur() {
    int i = blockIdx.x * blockDim.x + threadIdx.x;
    if (i < N_NODES) g_cur[i] = g_off[i];
}

__global__ void k_scatter(const int* __restrict__ edges) {
    int e = blockIdx.x * blockDim.x + threadIdx.x;
    if (e < N_EDGES) {
        int dst = edges[2 * e + 1];
        int p = atomicAdd(&g_cur[dst], 1);
        g_csr[p] = edges[2 * e];
    }
}

// --------------------------------- GEMM --------------------------------------
// C[M,N] = A[M,K] @ B[K,N], fp32, 64x64 block tile, 4x4 micro tile, BK=16.
__global__ __launch_bounds__(256) void k_gemm(const float* __restrict__ A,
                                              const float* __restrict__ B,
                                              float* __restrict__ C,
                                              int M, int N, int K) {
    __shared__ __align__(16) float As[16][68];
    __shared__ __align__(16) float Bs[16][68];
    int tid = threadIdx.x;
    int tx = tid & 15, ty = tid >> 4;
    int mBase = blockIdx.y * 64, nBase = blockIdx.x * 64;
    float acc[4][4] = {};
    for (int k0 = 0; k0 < K; k0 += 16) {
        #pragma unroll
        for (int i = 0; i < 4; i++) {
            int idx = tid + i * 256;
            int m = idx >> 4, k = idx & 15;
            int gm = mBase + m;
            As[k][m] = (gm < M) ? A[(size_t)gm * K + k0 + k] : 0.f;
            int kk = idx >> 6, n = idx & 63;
            int gn = nBase + n;
            Bs[kk][n] = (gn < N) ? B[(size_t)(k0 + kk) * N + gn] : 0.f;
        }
        __syncthreads();
        #pragma unroll
        for (int kk = 0; kk < 16; kk++) {
            float4 a4 = *reinterpret_cast<const float4*>(&As[kk][ty * 4]);
            float4 b4 = *reinterpret_cast<const float4*>(&Bs[kk][tx * 4]);
            float a[4] = {a4.x, a4.y, a4.z, a4.w};
            float b[4] = {b4.x, b4.y, b4.z, b4.w};
            #pragma unroll
            for (int i = 0; i < 4; i++)
                #pragma unroll
                for (int j = 0; j < 4; j++)
                    acc[i][j] += a[i] * b[j];
        }
        __syncthreads();
    }
    #pragma unroll
    for (int i = 0; i < 4; i++) {
        int gm = mBase + ty * 4 + i;
        if (gm >= M) continue;
        #pragma unroll
        for (int j = 0; j < 4; j++) {
            int gn = nBase + tx * 4 + j;
            if (gn < N) C[(size_t)gm * N + gn] = acc[i][j];
        }
    }
}

// ------------------------- attention scores e_s / e_d -------------------------
// warp per (node, head): es[n,h] = dot(h[n,h,:], a_src[h,:]), ed likewise.
__global__ void k_scores(const float* __restrict__ h, const float* __restrict__ a_src,
                         const float* __restrict__ a_dst, float* __restrict__ es,
                         float* __restrict__ ed, int H, int U) {
    int gw = (blockIdx.x * blockDim.x + threadIdx.x) >> 5;
    int lane = threadIdx.x & 31;
    if (gw >= N_NODES * H) return;
    int hh = gw % H;
    const float* hp = h + (size_t)gw * U;  // layout [n][H][U] contiguous
    float s1 = 0.f, s2 = 0.f;
    for (int u = lane; u < U; u += 32) {
        float v = hp[u];
        s1 += v * a_src[hh * U + u];
        s2 += v * a_dst[hh * U + u];
    }
    #pragma unroll
    for (int o = 16; o > 0; o >>= 1) {
        s1 += __shfl_xor_sync(0xffffffffu, s1, o);
        s2 += __shfl_xor_sync(0xffffffffu, s2, o);
    }
    if (lane == 0) { es[gw] = s1; ed[gw] = s2; }
}

// --------------------- per-dst softmax + message aggregation ------------------
// one block (128 threads) per dst node; CSR gather, no atomics.
__global__ __launch_bounds__(128) void k_aggregate(
    const float* __restrict__ h, const float* __restrict__ es,
    const float* __restrict__ ed, const float* __restrict__ res,
    float* __restrict__ out, int H, int U, int avgMerge, int doElu) {
    int n = blockIdx.x;
    int tid = threadIdx.x;
    int lane = tid & 31, wid = tid >> 5;
    int beg = g_off[n], end = g_off[n + 1];
    int deg = end - beg;
    __shared__ float warpred[4];
    __shared__ float s_m, s_inv;
    float accAvg = 0.f;
    for (int hh = 0; hh < H; hh++) {
        float edv = ed[n * H + hh];
        // pass 1: max over incident edges (after leaky relu)
        float mx = -1e30f;
        for (int i = tid; i < deg; i += 128) {
            int s = g_csr[beg + i];
            float e = es[s * H + hh] + edv;
            e = (e > 0.f) ? e : 0.2f * e;
            mx = fmaxf(mx, e);
        }
        #pragma unroll
        for (int o = 16; o > 0; o >>= 1) mx = fmaxf(mx, __shfl_xor_sync(0xffffffffu, mx, o));
        if (lane == 0) warpred[wid] = mx;
        __syncthreads();
        if (tid == 0) {
            float m = fmaxf(fmaxf(warpred[0], warpred[1]), fmaxf(warpred[2], warpred[3]));
            s_m = (deg > 0) ? m : 0.f;   // segment_max of empty -> 0 (isfinite fixup)
        }
        __syncthreads();
        float m = s_m;
        // pass 2: denom
        float sum = 0.f;
        for (int i = tid; i < deg; i += 128) {
            int s = g_csr[beg + i];
            float e = es[s * H + hh] + edv;
            e = (e > 0.f) ? e : 0.2f * e;
            sum += expf(e - m);
        }
        #pragma unroll
        for (int o = 16; o > 0; o >>= 1) sum += __shfl_xor_sync(0xffffffffu, sum, o);
        if (lane == 0) warpred[wid] = sum;
        __syncthreads();
        if (tid == 0) {
            float d = warpred[0] + warpred[1] + warpred[2] + warpred[3];
            s_inv = 1.0f / fmaxf(d, 1e-9f);
        }
        __syncthreads();
        float inv = s_inv;
        // pass 3: weighted accumulation; thread tid owns feature channel u=tid
        float acc = 0.f;
        for (int i = 0; i < deg; i++) {
            int s = g_csr[beg + i];
            float e = es[s * H + hh] + edv;
            e = (e > 0.f) ? e : 0.2f * e;
            float w = expf(e - m) * inv;
            if (tid < U) acc += w * h[((size_t)s * H + hh) * U + tid];
        }
        if (avgMerge) {
            accAvg += acc;
        } else if (tid < U) {
            float v = acc + res[(size_t)n * (H * U) + hh * U + tid];
            if (doElu) v = (v > 0.f) ? v : (expf(v) - 1.f);
            out[(size_t)n * (H * U) + hh * U + tid] = v;
        }
        __syncthreads();  // protect warpred / s_m reuse across heads
    }
    if (avgMerge && tid < U) {
        float v = accAvg / (float)H + res[(size_t)n * U + tid];
        if (doElu) v = (v > 0.f) ? v : (expf(v) - 1.f);
        out[(size_t)n * U + tid] = v;
    }
}

// ------------------------------- launcher ------------------------------------
extern "C" void kernel_launch(void* const* d_in, const int* in_sizes, int n_in,
                              void* d_out, int out_size) {
    const float* x    = (const float*)d_in[0];
    const int*   edges= (const int*)d_in[1];
    const float* W1   = (const float*)d_in[2];
    const float* a1s  = (const float*)d_in[3];
    const float* a1d  = (const float*)d_in[4];
    const float* R1   = (const float*)d_in[5];
    const float* W2   = (const float*)d_in[6];
    const float* a2s  = (const float*)d_in[7];
    const float* a2d  = (const float*)d_in[8];
    const float* W3   = (const float*)d_in[9];
    const float* a3s  = (const float*)d_in[10];
    const float* a3d  = (const float*)d_in[11];
    const float* R3   = (const float*)d_in[12];
    float* out = (float*)d_out;

    float *hbuf, *xa, *xb, *es, *ed;
    cudaGetSymbolAddress((void**)&hbuf, g_h);
    cudaGetSymbolAddress((void**)&xa, g_xa);
    cudaGetSymbolAddress((void**)&xb, g_xb);
    cudaGetSymbolAddress((void**)&es, g_es);
    cudaGetSymbolAddress((void**)&ed, g_ed);

    // CSR build (edges grouped by dst)
    k_zero_cnt<<<(N_NODES + 256) / 256, 256>>>();
    k_count<<<(N_EDGES + 255) / 256, 256>>>(edges);
    k_scan<<<1, 1024>>>();
    k_initcur<<<(N_NODES + 255) / 256, 256>>>();
    k_scatter<<<(N_EDGES + 255) / 256, 256>>>(edges);

    dim3 gN512((512 + 63) / 64, (N_NODES + 63) / 64);
    dim3 gN726((726 + 63) / 64, (N_NODES + 63) / 64);
    dim3 gN121((121 + 63) / 64, (N_NODES + 63) / 64);

    // ---- layer 1: H=4, U=128, concat, residual x@R1, ELU
    k_gemm<<<gN512, 256>>>(x, W1, hbuf, N_NODES, 512, 128);
    k_gemm<<<gN512, 256>>>(x, R1, xa, N_NODES, 512, 128);
    k_scores<<<(N_NODES * 4 * 32 + 255) / 256, 256>>>(hbuf, a1s, a1d, es, ed, 4, 128);
    k_aggregate<<<N_NODES, 128>>>(hbuf, es, ed, xa, xb, 4, 128, 0, 1);

    // ---- layer 2: H=4, U=128, concat, residual = x1, ELU
    k_gemm<<<gN512, 256>>>(xb, W2, hbuf, N_NODES, 512, 512);
    k_scores<<<(N_NODES * 4 * 32 + 255) / 256, 256>>>(hbuf, a2s, a2d, es, ed, 4, 128);
    k_aggregate<<<N_NODES, 128>>>(hbuf, es, ed, xb, xa, 4, 128, 0, 1);

    // ---- layer 3: H=6, U=121, avg merge, residual x2@R3, identity
    k_gemm<<<gN726, 256>>>(xa, W3, hbuf, N_NODES, 726, 512);
    k_gemm<<<gN121, 256>>>(xa, R3, xb, N_NODES, 121, 512);
    k_scores<<<(N_NODES * 6 * 32 + 255) / 256, 256>>>(hbuf, a3s, a3d, es, ed, 6, 121);
    k_aggregate<<<N_NODES, 128>>>(hbuf, es, ed, xb, out, 6, 121, 1, 0);
}

// round 2
// speedup vs baseline: 1.4610x; 1.4610x over previous
#include <cuda_runtime.h>
#include <math.h>
#include <stdint.h>

#define N_NODES 50000
#define N_EDGES 800000

// ---------------- scratch (device globals; no dynamic allocation) -------------
__device__ float g_h[(size_t)N_NODES * 726];   // h buffer (layers 1,2 use 512 of 726 width)
__device__ float g_xa[(size_t)N_NODES * 512];  // res1 -> x2
__device__ float g_xb[(size_t)N_NODES * 512];  // x1 -> res3
__device__ float g_es[N_NODES * 6];
__device__ float g_ed[N_NODES * 6];
__device__ int   g_cnt[N_NODES + 1];
__device__ int   g_off[N_NODES + 1];
__device__ int   g_cur[N_NODES];
__device__ int   g_csr[N_EDGES];               // src node of each edge, grouped by dst

// ------------------------------- CSR build -----------------------------------
__global__ void k_zero_cnt() {
    int i = blockIdx.x * blockDim.x + threadIdx.x;
    if (i <= N_NODES) g_cnt[i] = 0;
}

__global__ void k_count(const int* __restrict__ edges) {
    int e = blockIdx.x * blockDim.x + threadIdx.x;
    if (e < N_EDGES) atomicAdd(&g_cnt[edges[2 * e + 1]], 1);
}

__global__ void k_scan() {
    __shared__ int sh[1024];
    __shared__ int carry_s;
    int tid = threadIdx.x;
    if (tid == 0) { carry_s = 0; g_off[0] = 0; }
    __syncthreads();
    for (int base = 0; base < N_NODES; base += 1024) {
        int i = base + tid;
        int v = (i < N_NODES) ? g_cnt[i] : 0;
        sh[tid] = v;
        __syncthreads();
        for (int d = 1; d < 1024; d <<= 1) {
            int t = (tid >= d) ? sh[tid - d] : 0;
            __syncthreads();
            sh[tid] += t;
            __syncthreads();
        }
        if (i < N_NODES) g_off[i + 1] = carry_s + sh[tid];
        __syncthreads();
        if (tid == 0) carry_s += sh[1023];
        __syncthreads();
    }
}

__global__ void k_initcur() {
    int i = blockIdx.x * blockDim.x + threadIdx.x;
    if (i < N_NODES) g_cur[i] = g_off[i];
}

__global__ void k_scatter(const int* __restrict__ edges) {
    int e = blockIdx.x * blockDim.x + threadIdx.x;
    if (e < N_EDGES) {
        int dst = edges[2 * e + 1];
        int p = atomicAdd(&g_cur[dst], 1);
        g_csr[p] = edges[2 * e];
    }
}

// ------------------------------ TF32 TC GEMM ----------------------------------
// C[M,N] = A[M,K] @ B[K,N]; BM=128, BN=64, BK=32; 8 warps (4x2), warp tile 32x32.
// double-buffered smem via cp.async; mma.sync.m16n8k8 tf32 with rna conversion.
#define BM 128
#define BN 64
#define BK 32
#define ASTR 36                 // floats per A smem row (conflict-free: bank = 4g+c)
#define BSTR 72                 // floats per B smem row (conflict-free: bank = 8c+g)
#define ASZ (BM * ASTR)         // 4608 floats per buffer
#define BSZ (BK * BSTR)         // 2304 floats per buffer
#define GEMM_SMEM_BYTES ((2 * ASZ + 2 * BSZ) * 4)   // 55296

__device__ __forceinline__ uint32_t f2tf(float f) {
    uint32_t u;
    asm("cvt.rna.tf32.f32 %0, %1;" : "=r"(u) : "f"(f));
    return u;
}
__device__ __forceinline__ void cpa16(uint32_t s, const void* g, bool p) {
    asm volatile("cp.async.cg.shared.global [%0], [%1], 16, %2;" ::"r"(s), "l"(g), "r"(p ? 16 : 0));
}
__device__ __forceinline__ void cpa8(uint32_t s, const void* g, bool p) {
    asm volatile("cp.async.ca.shared.global [%0], [%1], 8, %2;" ::"r"(s), "l"(g), "r"(p ? 8 : 0));
}
__device__ __forceinline__ void cpa4(uint32_t s, const void* g, bool p) {
    asm volatile("cp.async.ca.shared.global [%0], [%1], 4, %2;" ::"r"(s), "l"(g), "r"(p ? 4 : 0));
}
__device__ __forceinline__ void cp_commit() { asm volatile("cp.async.commit_group;"); }

__device__ __forceinline__ void mma_tf32(float c[4], const uint32_t a[4], const uint32_t b[2]) {
    asm volatile(
        "mma.sync.aligned.m16n8k8.row.col.f32.tf32.tf32.f32 "
        "{%0,%1,%2,%3}, {%4,%5,%6,%7}, {%8,%9}, {%0,%1,%2,%3};"
        : "+f"(c[0]), "+f"(c[1]), "+f"(c[2]), "+f"(c[3])
        : "r"(a[0]), "r"(a[1]), "r"(a[2]), "r"(a[3]), "r"(b[0]), "r"(b[1]));
}

template <int VB>   // global B load width in bytes: 16, 8, or 4
__global__ __launch_bounds__(256) void k_gemm_tc(const float* __restrict__ A,
                                                 const float* __restrict__ B,
                                                 float* __restrict__ C,
                                                 int M, int N, int K) {
    extern __shared__ float smem[];
    float* As = smem;              // 2 buffers of [BM][ASTR]
    float* Bs = smem + 2 * ASZ;    // 2 buffers of [BK][BSTR]
    const int tid = threadIdx.x;
    const int lane = tid & 31, wid = tid >> 5;
    const int wm = wid & 3, wn = wid >> 2;           // 4 (M) x 2 (N) warps
    const int g = lane >> 2, c = lane & 3;           // fragment coords
    const int mBase = blockIdx.y * BM, nBase = blockIdx.x * BN;

    const uint32_t sAs = (uint32_t)__cvta_generic_to_shared(As);
    const uint32_t sBs = (uint32_t)__cvta_generic_to_shared(Bs);

    // A loader indices: 4 x float4 per thread
    const int arow = tid >> 3;
    const int acol = (tid & 7) * 4;

    float acc[2][4][4];
    #pragma unroll
    for (int mt = 0; mt < 2; mt++)
        #pragma unroll
        for (int nt = 0; nt < 4; nt++)
            #pragma unroll
            for (int i = 0; i < 4; i++) acc[mt][nt][i] = 0.f;

    auto loadTile = [&](int k0, int buf) {
        uint32_t aB = sAs + (uint32_t)(buf * ASZ * 4);
        #pragma unroll
        for (int i = 0; i < 4; i++) {
            int row = arow + i * 32;
            int gm = mBase + row;
            cpa16(aB + (uint32_t)((row * ASTR + acol) * 4),
                  A + (size_t)gm * K + k0 + acol, gm < M);
        }
        uint32_t bB = sBs + (uint32_t)(buf * BSZ * 4);
        if (VB == 16) {
            #pragma unroll
            for (int v = 0; v < 2; v++) {
                int vid = tid + v * 256;
                int brow = vid >> 4, bcol = (vid & 15) * 4;
                int gn = nBase + bcol;
                cpa16(bB + (uint32_t)((brow * BSTR + bcol) * 4),
                      B + (size_t)(k0 + brow) * N + gn, gn < N);
            }
        } else if (VB == 8) {
            #pragma unroll
            for (int v = 0; v < 4; v++) {
                int vid = tid + v * 256;
                int brow = vid >> 5, bcol = (vid & 31) * 2;
                int gn = nBase + bcol;
                cpa8(bB + (uint32_t)((brow * BSTR + bcol) * 4),
                     B + (size_t)(k0 + brow) * N + gn, gn < N);
            }
        } else {
            #pragma unroll
            for (int v = 0; v < 8; v++) {
                int vid = tid + v * 256;
                int brow = vid >> 6, bcol = vid & 63;
                int gn = nBase + bcol;
                cpa4(bB + (uint32_t)((brow * BSTR + bcol) * 4),
                     B + (size_t)(k0 + brow) * N + gn, gn < N);
            }
        }
    };

    const int ntiles = K / BK;
    loadTile(0, 0);
    cp_commit();

    for (int t = 0; t < ntiles; t++) {
        int buf = t & 1;
        if (t + 1 < ntiles) {
            loadTile((t + 1) * BK, (t + 1) & 1);
            cp_commit();
            asm volatile("cp.async.wait_group 1;");
        } else {
            asm volatile("cp.async.wait_group 0;");
        }
        __syncthreads();

        const float* Ab = As + buf * ASZ;
        const float* Bb = Bs + buf * BSZ;
        #pragma unroll
        for (int kk = 0; kk < 4; kk++) {
            uint32_t af[2][4], bf[4][2];
            #pragma unroll
            for (int mt = 0; mt < 2; mt++) {
                const float* ap = Ab + (wm * 32 + mt * 16 + g) * ASTR + kk * 8 + c;
                af[mt][0] = f2tf(ap[0]);
                af[mt][1] = f2tf(ap[8 * ASTR]);
                af[mt][2] = f2tf(ap[4]);
                af[mt][3] = f2tf(ap[8 * ASTR + 4]);
            }
            #pragma unroll
            for (int nt = 0; nt < 4; nt++) {
                const float* bp = Bb + (kk * 8 + c) * BSTR + wn * 32 + nt * 8 + g;
                bf[nt][0] = f2tf(bp[0]);
                bf[nt][1] = f2tf(bp[4 * BSTR]);
            }
            #pragma unroll
            for (int mt = 0; mt < 2; mt++)
                #pragma unroll
                for (int nt = 0; nt < 4; nt++)
                    mma_tf32(acc[mt][nt], af[mt], bf[nt]);
        }
        __syncthreads();
    }

    // epilogue
    #pragma unroll
    for (int mt = 0; mt < 2; mt++) {
        int r0 = mBase + wm * 32 + mt * 16 + g;
        int r1 = r0 + 8;
        #pragma unroll
        for (int nt = 0; nt < 4; nt++) {
            int col = nBase + wn * 32 + nt * 8 + 2 * c;
            if (r0 < M) {
                if (col < N)     C[(size_t)r0 * N + col]     = acc[mt][nt][0];
                if (col + 1 < N) C[(size_t)r0 * N + col + 1] = acc[mt][nt][1];
            }
            if (r1 < M) {
                if (col < N)     C[(size_t)r1 * N + col]     = acc[mt][nt][2];
                if (col + 1 < N) C[(size_t)r1 * N + col + 1] = acc[mt][nt][3];
            }
        }
    }
}

// ------------------------- attention scores e_s / e_d -------------------------
__global__ void k_scores(const float* __restrict__ h, const float* __restrict__ a_src,
                         const float* __restrict__ a_dst, float* __restrict__ es,
                         float* __restrict__ ed, int H, int U) {
    int gw = (blockIdx.x * blockDim.x + threadIdx.x) >> 5;
    int lane = threadIdx.x & 31;
    if (gw >= N_NODES * H) return;
    int hh = gw % H;
    const float* hp = h + (size_t)gw * U;
    float s1 = 0.f, s2 = 0.f;
    for (int u = lane; u < U; u += 32) {
        float v = hp[u];
        s1 += v * a_src[hh * U + u];
        s2 += v * a_dst[hh * U + u];
    }
    #pragma unroll
    for (int o = 16; o > 0; o >>= 1) {
        s1 += __shfl_xor_sync(0xffffffffu, s1, o);
        s2 += __shfl_xor_sync(0xffffffffu, s2, o);
    }
    if (lane == 0) { es[gw] = s1; ed[gw] = s2; }
}

// --------------------- per-dst softmax + message aggregation ------------------
__global__ __launch_bounds__(128) void k_aggregate(
    const float* __restrict__ h, const float* __restrict__ es,
    const float* __restrict__ ed, const float* __restrict__ res,
    float* __restrict__ out, int H, int U, int avgMerge, int doElu) {
    int n = blockIdx.x;
    int tid = threadIdx.x;
    int lane = tid & 31, wid = tid >> 5;
    int beg = g_off[n], end = g_off[n + 1];
    int deg = end - beg;
    __shared__ float warpred[4];
    __shared__ float s_m, s_inv;
    float accAvg = 0.f;
    for (int hh = 0; hh < H; hh++) {
        float edv = ed[n * H + hh];
        float mx = -1e30f;
        for (int i = tid; i < deg; i += 128) {
            int s = g_csr[beg + i];
            float e = es[s * H + hh] + edv;
            e = (e > 0.f) ? e : 0.2f * e;
            mx = fmaxf(mx, e);
        }
        #pragma unroll
        for (int o = 16; o > 0; o >>= 1) mx = fmaxf(mx, __shfl_xor_sync(0xffffffffu, mx, o));
        if (lane == 0) warpred[wid] = mx;
        __syncthreads();
        if (tid == 0) {
            float m = fmaxf(fmaxf(warpred[0], warpred[1]), fmaxf(warpred[2], warpred[3]));
            s_m = (deg > 0) ? m : 0.f;
        }
        __syncthreads();
        float m = s_m;
        float sum = 0.f;
        for (int i = tid; i < deg; i += 128) {
            int s = g_csr[beg + i];
            float e = es[s * H + hh] + edv;
            e = (e > 0.f) ? e : 0.2f * e;
            sum += expf(e - m);
        }
        #pragma unroll
        for (int o = 16; o > 0; o >>= 1) sum += __shfl_xor_sync(0xffffffffu, sum, o);
        if (lane == 0) warpred[wid] = sum;
        __syncthreads();
        if (tid == 0) {
            float d = warpred[0] + warpred[1] + warpred[2] + warpred[3];
            s_inv = 1.0f / fmaxf(d, 1e-9f);
        }
        __syncthreads();
        float inv = s_inv;
        float acc = 0.f;
        for (int i = 0; i < deg; i++) {
            int s = g_csr[beg + i];
            float e = es[s * H + hh] + edv;
            e = (e > 0.f) ? e : 0.2f * e;
            float w = expf(e - m) * inv;
            if (tid < U) acc += w * h[((size_t)s * H + hh) * U + tid];
        }
        if (avgMerge) {
            accAvg += acc;
        } else if (tid < U) {
            float v = acc + res[(size_t)n * (H * U) + hh * U + tid];
            if (doElu) v = (v > 0.f) ? v : (expf(v) - 1.f);
            out[(size_t)n * (H * U) + hh * U + tid] = v;
        }
        __syncthreads();
    }
    if (avgMerge && tid < U) {
        float v = accAvg / (float)H + res[(size_t)n * U + tid];
        if (doElu) v = (v > 0.f) ? v : (expf(v) - 1.f);
        out[(size_t)n * U + tid] = v;
    }
}

// ------------------------------- launcher ------------------------------------
static void launch_gemm(const float* A, const float* B, float* C, int M, int N, int K) {
    dim3 grid((N + BN - 1) / BN, (M + BM - 1) / BM);
    if ((N & 3) == 0) {
        cudaFuncSetAttribute(k_gemm_tc<16>, cudaFuncAttributeMaxDynamicSharedMemorySize, GEMM_SMEM_BYTES);
        k_gemm_tc<16><<<grid, 256, GEMM_SMEM_BYTES>>>(A, B, C, M, N, K);
    } else if ((N & 1) == 0) {
        cudaFuncSetAttribute(k_gemm_tc<8>, cudaFuncAttributeMaxDynamicSharedMemorySize, GEMM_SMEM_BYTES);
        k_gemm_tc<8><<<grid, 256, GEMM_SMEM_BYTES>>>(A, B, C, M, N, K);
    } else {
        cudaFuncSetAttribute(k_gemm_tc<4>, cudaFuncAttributeMaxDynamicSharedMemorySize, GEMM_SMEM_BYTES);
        k_gemm_tc<4><<<grid, 256, GEMM_SMEM_BYTES>>>(A, B, C, M, N, K);
    }
}

extern "C" void kernel_launch(void* const* d_in, const int* in_sizes, int n_in,
                              void* d_out, int out_size) {
    const float* x    = (const float*)d_in[0];
    const int*   edges= (const int*)d_in[1];
    const float* W1   = (const float*)d_in[2];
    const float* a1s  = (const float*)d_in[3];
    const float* a1d  = (const float*)d_in[4];
    const float* R1   = (const float*)d_in[5];
    const float* W2   = (const float*)d_in[6];
    const float* a2s  = (const float*)d_in[7];
    const float* a2d  = (const float*)d_in[8];
    const float* W3   = (const float*)d_in[9];
    const float* a3s  = (const float*)d_in[10];
    const float* a3d  = (const float*)d_in[11];
    const float* R3   = (const float*)d_in[12];
    float* out = (float*)d_out;

    float *hbuf, *xa, *xb, *es, *ed;
    cudaGetSymbolAddress((void**)&hbuf, g_h);
    cudaGetSymbolAddress((void**)&xa, g_xa);
    cudaGetSymbolAddress((void**)&xb, g_xb);
    cudaGetSymbolAddress((void**)&es, g_es);
    cudaGetSymbolAddress((void**)&ed, g_ed);

    // CSR build (edges grouped by dst)
    k_zero_cnt<<<(N_NODES + 256) / 256, 256>>>();
    k_count<<<(N_EDGES + 255) / 256, 256>>>(edges);
    k_scan<<<1, 1024>>>();
    k_initcur<<<(N_NODES + 255) / 256, 256>>>();
    k_scatter<<<(N_EDGES + 255) / 256, 256>>>(edges);

    // ---- layer 1: H=4, U=128, concat, residual x@R1, ELU
    launch_gemm(x, W1, hbuf, N_NODES, 512, 128);
    launch_gemm(x, R1, xa, N_NODES, 512, 128);
    k_scores<<<(N_NODES * 4 * 32 + 255) / 256, 256>>>(hbuf, a1s, a1d, es, ed, 4, 128);
    k_aggregate<<<N_NODES, 128>>>(hbuf, es, ed, xa, xb, 4, 128, 0, 1);

    // ---- layer 2: H=4, U=128, concat, residual = x1, ELU
    launch_gemm(xb, W2, hbuf, N_NODES, 512, 512);
    k_scores<<<(N_NODES * 4 * 32 + 255) / 256, 256>>>(hbuf, a2s, a2d, es, ed, 4, 128);
    k_aggregate<<<N_NODES, 128>>>(hbuf, es, ed, xb, xa, 4, 128, 0, 1);

    // ---- layer 3: H=6, U=121, avg merge, residual x2@R3, identity
    launch_gemm(xa, W3, hbuf, N_NODES, 726, 512);
    launch_gemm(xa, R3, xb, N_NODES, 121, 512);
    k_scores<<<(N_NODES * 6 * 32 + 255) / 256, 256>>>(hbuf, a3s, a3d, es, ed, 6, 121);
    k_aggregate<<<N_NODES, 128>>>(hbuf, es, ed, xb, out, 6, 121, 1, 0);
}

// round 3
// speedup vs baseline: 1.7988x; 1.2313x over previous
#include <cuda_runtime.h>
#include <math.h>
#include <stdint.h>

#define N_NODES 50000
#define N_EDGES 800000

// ---------------- scratch (device globals; no dynamic allocation) -------------
__device__ float g_h[(size_t)N_NODES * 726];
__device__ float g_xa[(size_t)N_NODES * 512];
__device__ float g_xb[(size_t)N_NODES * 512];
__device__ float g_es[N_NODES * 6];
__device__ float g_ed[N_NODES * 6];
__device__ float g_w[(size_t)N_EDGES * 6];     // softmax weight per (edge, head)
__device__ int   g_cnt[N_NODES + 1];
__device__ int   g_off[N_NODES + 1];
__device__ int   g_cur[N_NODES];
__device__ int   g_csr[N_EDGES];               // src node per edge, grouped by dst

// ------------------------------- CSR build -----------------------------------
__global__ void k_zero_cnt() {
    int i = blockIdx.x * blockDim.x + threadIdx.x;
    if (i <= N_NODES) g_cnt[i] = 0;
}
__global__ void k_count(const int* __restrict__ edges) {
    int e = blockIdx.x * blockDim.x + threadIdx.x;
    if (e < N_EDGES) atomicAdd(&g_cnt[edges[2 * e + 1]], 1);
}
__global__ void k_scan() {
    __shared__ int sh[1024];
    __shared__ int carry_s;
    int tid = threadIdx.x;
    if (tid == 0) { carry_s = 0; g_off[0] = 0; }
    __syncthreads();
    for (int base = 0; base < N_NODES; base += 1024) {
        int i = base + tid;
        int v = (i < N_NODES) ? g_cnt[i] : 0;
        sh[tid] = v;
        __syncthreads();
        for (int d = 1; d < 1024; d <<= 1) {
            int t = (tid >= d) ? sh[tid - d] : 0;
            __syncthreads();
            sh[tid] += t;
            __syncthreads();
        }
        if (i < N_NODES) g_off[i + 1] = carry_s + sh[tid];
        __syncthreads();
        if (tid == 0) carry_s += sh[1023];
        __syncthreads();
    }
}
__global__ void k_initcur() {
    int i = blockIdx.x * blockDim.x + threadIdx.x;
    if (i < N_NODES) g_cur[i] = g_off[i];
}
__global__ void k_scatter(const int* __restrict__ edges) {
    int e = blockIdx.x * blockDim.x + threadIdx.x;
    if (e < N_EDGES) {
        int dst = edges[2 * e + 1];
        int p = atomicAdd(&g_cur[dst], 1);
        g_csr[p] = edges[2 * e];
    }
}

// ------------------------------ TF32 TC GEMM ----------------------------------
#define BM 128
#define BN 64
#define BK 32
#define ASTR 36
#define BSTR 72
#define ASZ (BM * ASTR)
#define BSZ (BK * BSTR)
#define GEMM_SMEM_BYTES ((2 * ASZ + 2 * BSZ) * 4)

__device__ __forceinline__ uint32_t f2tf(float f) {
    uint32_t u;
    asm("cvt.rna.tf32.f32 %0, %1;" : "=r"(u) : "f"(f));
    return u;
}
__device__ __forceinline__ void cpa16(uint32_t s, const void* g, bool p) {
    asm volatile("cp.async.cg.shared.global [%0], [%1], 16, %2;" ::"r"(s), "l"(g), "r"(p ? 16 : 0));
}
__device__ __forceinline__ void cpa8(uint32_t s, const void* g, bool p) {
    asm volatile("cp.async.ca.shared.global [%0], [%1], 8, %2;" ::"r"(s), "l"(g), "r"(p ? 8 : 0));
}
__device__ __forceinline__ void cpa4(uint32_t s, const void* g, bool p) {
    asm volatile("cp.async.ca.shared.global [%0], [%1], 4, %2;" ::"r"(s), "l"(g), "r"(p ? 4 : 0));
}
__device__ __forceinline__ void cp_commit() { asm volatile("cp.async.commit_group;"); }

__device__ __forceinline__ void mma_tf32(float c[4], const uint32_t a[4], const uint32_t b[2]) {
    asm volatile(
        "mma.sync.aligned.m16n8k8.row.col.f32.tf32.tf32.f32 "
        "{%0,%1,%2,%3}, {%4,%5,%6,%7}, {%8,%9}, {%0,%1,%2,%3};"
        : "+f"(c[0]), "+f"(c[1]), "+f"(c[2]), "+f"(c[3])
        : "r"(a[0]), "r"(a[1]), "r"(a[2]), "r"(a[3]), "r"(b[0]), "r"(b[1]));
}

template <int VB>
__global__ __launch_bounds__(256) void k_gemm_tc(const float* __restrict__ A,
                                                 const float* __restrict__ B,
                                                 float* __restrict__ C,
                                                 int M, int N, int K) {
    extern __shared__ float smem[];
    float* As = smem;
    float* Bs = smem + 2 * ASZ;
    const int tid = threadIdx.x;
    const int lane = tid & 31, wid = tid >> 5;
    const int wm = wid & 3, wn = wid >> 2;
    const int g = lane >> 2, c = lane & 3;
    const int mBase = blockIdx.y * BM, nBase = blockIdx.x * BN;

    const uint32_t sAs = (uint32_t)__cvta_generic_to_shared(As);
    const uint32_t sBs = (uint32_t)__cvta_generic_to_shared(Bs);

    const int arow = tid >> 3;
    const int acol = (tid & 7) * 4;

    float acc[2][4][4];
    #pragma unroll
    for (int mt = 0; mt < 2; mt++)
        #pragma unroll
        for (int nt = 0; nt < 4; nt++)
            #pragma unroll
            for (int i = 0; i < 4; i++) acc[mt][nt][i] = 0.f;

    auto loadTile = [&](int k0, int buf) {
        uint32_t aB = sAs + (uint32_t)(buf * ASZ * 4);
        #pragma unroll
        for (int i = 0; i < 4; i++) {
            int row = arow + i * 32;
            int gm = mBase + row;
            cpa16(aB + (uint32_t)((row * ASTR + acol) * 4),
                  A + (size_t)gm * K + k0 + acol, gm < M);
        }
        uint32_t bB = sBs + (uint32_t)(buf * BSZ * 4);
        if (VB == 16) {
            #pragma unroll
            for (int v = 0; v < 2; v++) {
                int vid = tid + v * 256;
                int brow = vid >> 4, bcol = (vid & 15) * 4;
                int gn = nBase + bcol;
                cpa16(bB + (uint32_t)((brow * BSTR + bcol) * 4),
                      B + (size_t)(k0 + brow) * N + gn, gn < N);
            }
        } else if (VB == 8) {
            #pragma unroll
            for (int v = 0; v < 4; v++) {
                int vid = tid + v * 256;
                int brow = vid >> 5, bcol = (vid & 31) * 2;
                int gn = nBase + bcol;
                cpa8(bB + (uint32_t)((brow * BSTR + bcol) * 4),
                     B + (size_t)(k0 + brow) * N + gn, gn < N);
            }
        } else {
            #pragma unroll
            for (int v = 0; v < 8; v++) {
                int vid = tid + v * 256;
                int brow = vid >> 6, bcol = vid & 63;
                int gn = nBase + bcol;
                cpa4(bB + (uint32_t)((brow * BSTR + bcol) * 4),
                     B + (size_t)(k0 + brow) * N + gn, gn < N);
            }
        }
    };

    const int ntiles = K / BK;
    loadTile(0, 0);
    cp_commit();

    for (int t = 0; t < ntiles; t++) {
        int buf = t & 1;
        if (t + 1 < ntiles) {
            loadTile((t + 1) * BK, (t + 1) & 1);
            cp_commit();
            asm volatile("cp.async.wait_group 1;");
        } else {
            asm volatile("cp.async.wait_group 0;");
        }
        __syncthreads();

        const float* Ab = As + buf * ASZ;
        const float* Bb = Bs + buf * BSZ;
        #pragma unroll
        for (int kk = 0; kk < 4; kk++) {
            uint32_t af[2][4], bf[4][2];
            #pragma unroll
            for (int mt = 0; mt < 2; mt++) {
                const float* ap = Ab + (wm * 32 + mt * 16 + g) * ASTR + kk * 8 + c;
                af[mt][0] = f2tf(ap[0]);
                af[mt][1] = f2tf(ap[8 * ASTR]);
                af[mt][2] = f2tf(ap[4]);
                af[mt][3] = f2tf(ap[8 * ASTR + 4]);
            }
            #pragma unroll
            for (int nt = 0; nt < 4; nt++) {
                const float* bp = Bb + (kk * 8 + c) * BSTR + wn * 32 + nt * 8 + g;
                bf[nt][0] = f2tf(bp[0]);
                bf[nt][1] = f2tf(bp[4 * BSTR]);
            }
            #pragma unroll
            for (int mt = 0; mt < 2; mt++)
                #pragma unroll
                for (int nt = 0; nt < 4; nt++)
                    mma_tf32(acc[mt][nt], af[mt], bf[nt]);
        }
        __syncthreads();
    }

    #pragma unroll
    for (int mt = 0; mt < 2; mt++) {
        int r0 = mBase + wm * 32 + mt * 16 + g;
        int r1 = r0 + 8;
        #pragma unroll
        for (int nt = 0; nt < 4; nt++) {
            int col = nBase + wn * 32 + nt * 8 + 2 * c;
            if (r0 < M) {
                if (col < N)     C[(size_t)r0 * N + col]     = acc[mt][nt][0];
                if (col + 1 < N) C[(size_t)r0 * N + col + 1] = acc[mt][nt][1];
            }
            if (r1 < M) {
                if (col < N)     C[(size_t)r1 * N + col]     = acc[mt][nt][2];
                if (col + 1 < N) C[(size_t)r1 * N + col + 1] = acc[mt][nt][3];
            }
        }
    }
}

// ------------------------- attention scores e_s / e_d -------------------------
__global__ void k_scores(const float* __restrict__ h, const float* __restrict__ a_src,
                         const float* __restrict__ a_dst, float* __restrict__ es,
                         float* __restrict__ ed, int H, int U) {
    int gw = (blockIdx.x * blockDim.x + threadIdx.x) >> 5;
    int lane = threadIdx.x & 31;
    if (gw >= N_NODES * H) return;
    int hh = gw % H;
    const float* hp = h + (size_t)gw * U;
    float s1 = 0.f, s2 = 0.f;
    for (int u = lane; u < U; u += 32) {
        float v = hp[u];
        s1 += v * a_src[hh * U + u];
        s2 += v * a_dst[hh * U + u];
    }
    #pragma unroll
    for (int o = 16; o > 0; o >>= 1) {
        s1 += __shfl_xor_sync(0xffffffffu, s1, o);
        s2 += __shfl_xor_sync(0xffffffffu, s2, o);
    }
    if (lane == 0) { es[gw] = s1; ed[gw] = s2; }
}

// --------------------- softmax weight precompute (per dst, per head) ----------
__global__ __launch_bounds__(128) void k_weights(const float* __restrict__ es,
                                                 const float* __restrict__ ed,
                                                 int H) {
    int n = blockIdx.x;
    int tid = threadIdx.x;
    int lane = tid & 31, wid = tid >> 5;
    int beg = g_off[n], deg = g_off[n + 1] - beg;
    if (deg == 0) return;
    __shared__ float warpred[4];
    __shared__ float s_m, s_inv;
    for (int hh = 0; hh < H; hh++) {
        float edv = ed[n * H + hh];
        float mx = -1e30f;
        for (int i = tid; i < deg; i += 128) {
            int s = g_csr[beg + i];
            float e = es[s * H + hh] + edv;
            e = (e > 0.f) ? e : 0.2f * e;
            mx = fmaxf(mx, e);
        }
        #pragma unroll
        for (int o = 16; o > 0; o >>= 1) mx = fmaxf(mx, __shfl_xor_sync(0xffffffffu, mx, o));
        if (lane == 0) warpred[wid] = mx;
        __syncthreads();
        if (tid == 0)
            s_m = fmaxf(fmaxf(warpred[0], warpred[1]), fmaxf(warpred[2], warpred[3]));
        __syncthreads();
        float m = s_m;
        float sum = 0.f;
        for (int i = tid; i < deg; i += 128) {
            int s = g_csr[beg + i];
            float e = es[s * H + hh] + edv;
            e = (e > 0.f) ? e : 0.2f * e;
            sum += expf(e - m);
        }
        #pragma unroll
        for (int o = 16; o > 0; o >>= 1) sum += __shfl_xor_sync(0xffffffffu, sum, o);
        if (lane == 0) warpred[wid] = sum;
        __syncthreads();
        if (tid == 0)
            s_inv = 1.0f / fmaxf(warpred[0] + warpred[1] + warpred[2] + warpred[3], 1e-9f);
        __syncthreads();
        float inv = s_inv;
        for (int i = tid; i < deg; i += 128) {
            int s = g_csr[beg + i];
            float e = es[s * H + hh] + edv;
            e = (e > 0.f) ? e : 0.2f * e;
            g_w[(size_t)(beg + i) * H + hh] = expf(e - m) * inv;
        }
        __syncthreads();
    }
}

// ---------------- weighted aggregation, layers 1/2 (H=4, U=128) ---------------
// 512 threads = one thread per output channel of the full [H*U]=512 row.
__global__ __launch_bounds__(512) void k_agg512(const float* __restrict__ h,
                                                const float* __restrict__ res,
                                                float* __restrict__ out) {
    int n = blockIdx.x;
    int tid = threadIdx.x;
    int hh = tid >> 7;               // head = tid/128
    int beg = g_off[n], deg = g_off[n + 1] - beg;
    float acc = 0.f;
    int i = 0;
    for (; i + 4 <= deg; i += 4) {
        int s0 = g_csr[beg + i],     s1 = g_csr[beg + i + 1];
        int s2 = g_csr[beg + i + 2], s3 = g_csr[beg + i + 3];
        float w0 = g_w[(size_t)(beg + i) * 4 + hh];
        float w1 = g_w[(size_t)(beg + i + 1) * 4 + hh];
        float w2 = g_w[(size_t)(beg + i + 2) * 4 + hh];
        float w3 = g_w[(size_t)(beg + i + 3) * 4 + hh];
        float v0 = __ldg(h + (size_t)s0 * 512 + tid);
        float v1 = __ldg(h + (size_t)s1 * 512 + tid);
        float v2 = __ldg(h + (size_t)s2 * 512 + tid);
        float v3 = __ldg(h + (size_t)s3 * 512 + tid);
        acc += w0 * v0 + w1 * v1 + w2 * v2 + w3 * v3;
    }
    for (; i < deg; i++) {
        int s = g_csr[beg + i];
        float w = g_w[(size_t)(beg + i) * 4 + hh];
        acc += w * __ldg(h + (size_t)s * 512 + tid);
    }
    float v = acc + res[(size_t)n * 512 + tid];
    v = (v > 0.f) ? v : (expf(v) - 1.f);   // ELU
    out[(size_t)n * 512 + tid] = v;
}

// ---------------- weighted aggregation, layer 3 (H=6, U=121, avg) -------------
__global__ __launch_bounds__(768) void k_agg726(const float* __restrict__ h,
                                                const float* __restrict__ res,
                                                float* __restrict__ out) {
    __shared__ float sh[726];
    int n = blockIdx.x;
    int tid = threadIdx.x;
    int beg = g_off[n], deg = g_off[n + 1] - beg;
    if (tid < 726) {
        int hh = tid / 121;
        float acc = 0.f;
        int i = 0;
        for (; i + 4 <= deg; i += 4) {
            int s0 = g_csr[beg + i],     s1 = g_csr[beg + i + 1];
            int s2 = g_csr[beg + i + 2], s3 = g_csr[beg + i + 3];
            float w0 = g_w[(size_t)(beg + i) * 6 + hh];
            float w1 = g_w[(size_t)(beg + i + 1) * 6 + hh];
            float w2 = g_w[(size_t)(beg + i + 2) * 6 + hh];
            float w3 = g_w[(size_t)(beg + i + 3) * 6 + hh];
            float v0 = __ldg(h + (size_t)s0 * 726 + tid);
            float v1 = __ldg(h + (size_t)s1 * 726 + tid);
            float v2 = __ldg(h + (size_t)s2 * 726 + tid);
            float v3 = __ldg(h + (size_t)s3 * 726 + tid);
            acc += w0 * v0 + w1 * v1 + w2 * v2 + w3 * v3;
        }
        for (; i < deg; i++) {
            int s = g_csr[beg + i];
            float w = g_w[(size_t)(beg + i) * 6 + hh];
            acc += w * __ldg(h + (size_t)s * 726 + tid);
        }
        sh[tid] = acc;
    }
    __syncthreads();
    if (tid < 121) {
        float s = 0.f;
        #pragma unroll
        for (int hh = 0; hh < 6; hh++) s += sh[tid + hh * 121];
        out[(size_t)n * 121 + tid] = s * (1.f / 6.f) + res[(size_t)n * 121 + tid];
    }
}

// ------------------------------- launcher ------------------------------------
static void launch_gemm(const float* A, const float* B, float* C, int M, int N, int K) {
    dim3 grid((N + BN - 1) / BN, (M + BM - 1) / BM);
    if ((N & 3) == 0) {
        cudaFuncSetAttribute(k_gemm_tc<16>, cudaFuncAttributeMaxDynamicSharedMemorySize, GEMM_SMEM_BYTES);
        k_gemm_tc<16><<<grid, 256, GEMM_SMEM_BYTES>>>(A, B, C, M, N, K);
    } else if ((N & 1) == 0) {
        cudaFuncSetAttribute(k_gemm_tc<8>, cudaFuncAttributeMaxDynamicSharedMemorySize, GEMM_SMEM_BYTES);
        k_gemm_tc<8><<<grid, 256, GEMM_SMEM_BYTES>>>(A, B, C, M, N, K);
    } else {
        cudaFuncSetAttribute(k_gemm_tc<4>, cudaFuncAttributeMaxDynamicSharedMemorySize, GEMM_SMEM_BYTES);
        k_gemm_tc<4><<<grid, 256, GEMM_SMEM_BYTES>>>(A, B, C, M, N, K);
    }
}

extern "C" void kernel_launch(void* const* d_in, const int* in_sizes, int n_in,
                              void* d_out, int out_size) {
    const float* x    = (const float*)d_in[0];
    const int*   edges= (const int*)d_in[1];
    const float* W1   = (const float*)d_in[2];
    const float* a1s  = (const float*)d_in[3];
    const float* a1d  = (const float*)d_in[4];
    const float* R1   = (const float*)d_in[5];
    const float* W2   = (const float*)d_in[6];
    const float* a2s  = (const float*)d_in[7];
    const float* a2d  = (const float*)d_in[8];
    const float* W3   = (const float*)d_in[9];
    const float* a3s  = (const float*)d_in[10];
    const float* a3d  = (const float*)d_in[11];
    const float* R3   = (const float*)d_in[12];
    float* out = (float*)d_out;

    float *hbuf, *xa, *xb, *es, *ed;
    cudaGetSymbolAddress((void**)&hbuf, g_h);
    cudaGetSymbolAddress((void**)&xa, g_xa);
    cudaGetSymbolAddress((void**)&xb, g_xb);
    cudaGetSymbolAddress((void**)&es, g_es);
    cudaGetSymbolAddress((void**)&ed, g_ed);

    // CSR build (edges grouped by dst)
    k_zero_cnt<<<(N_NODES + 256) / 256, 256>>>();
    k_count<<<(N_EDGES + 255) / 256, 256>>>(edges);
    k_scan<<<1, 1024>>>();
    k_initcur<<<(N_NODES + 255) / 256, 256>>>();
    k_scatter<<<(N_EDGES + 255) / 256, 256>>>(edges);

    // ---- layer 1: H=4, U=128, concat, residual x@R1, ELU
    launch_gemm(x, W1, hbuf, N_NODES, 512, 128);
    launch_gemm(x, R1, xa, N_NODES, 512, 128);
    k_scores<<<(N_NODES * 4 * 32 + 255) / 256, 256>>>(hbuf, a1s, a1d, es, ed, 4, 128);
    k_weights<<<N_NODES, 128>>>(es, ed, 4);
    k_agg512<<<N_NODES, 512>>>(hbuf, xa, xb);

    // ---- layer 2: H=4, U=128, concat, residual = x1, ELU
    launch_gemm(xb, W2, hbuf, N_NODES, 512, 512);
    k_scores<<<(N_NODES * 4 * 32 + 255) / 256, 256>>>(hbuf, a2s, a2d, es, ed, 4, 128);
    k_weights<<<N_NODES, 128>>>(es, ed, 4);
    k_agg512<<<N_NODES, 512>>>(hbuf, xb, xa);

    // ---- layer 3: H=6, U=121, avg merge, residual x2@R3, identity
    launch_gemm(xa, W3, hbuf, N_NODES, 726, 512);
    launch_gemm(xa, R3, xb, N_NODES, 121, 512);
    k_scores<<<(N_NODES * 6 * 32 + 255) / 256, 256>>>(hbuf, a3s, a3d, es, ed, 6, 121);
    k_weights<<<N_NODES, 128>>>(es, ed, 6);
    k_agg726<<<N_NODES, 768>>>(hbuf, xb, out);
}